// round 17
// baseline (speedup 1.0000x reference)
#include <cuda_runtime.h>
#include <math.h>

// SpectralCirculantLayer: y = ifft(fft(x) * H) + bias, N=4096 per row, B=8192.
// rfft-4096 via c2c-2048 (even/odd pack), spectral multiply on bins 0..1023 (H
// truncated), one-sided inverse pack, irfft via c2c-2048.
// Radix 16*16*8 Stockham, 128 threads/CTA, ONE row per CTA, 4 CTAs/SM,
// stride-18 padding, STS.128 stage-1 writes, vectorized midstage->inv-s1
// layout (LDS/STS.128), dual-chain twiddles (R15 base, 88.2us).
// THIS ROUND: dynamic row scheduler. A global atomic counter (reset by a tiny
// kernel each launch) hands out rows; the next-row fetch is issued by thread 0
// right after the stage-1 barrier and consumed 5 barriers later, so the
// atomic's latency is fully hidden and no extra barrier is needed. Removes the
// ~4% static grid-stride tail imbalance (288 CTAs x 14 rows vs 320 x 13).

#define NTHREADS 128
#define SB16 2304   // 2048 + 2*(2048/16) padding (stride-18 rows, 16B aligned)

__device__ int g_row_counter;

__device__ __forceinline__ int pd(int i) { return i + ((i >> 4) << 1); }

__device__ __forceinline__ float2 cadd(float2 a, float2 b) { return make_float2(a.x + b.x, a.y + b.y); }
__device__ __forceinline__ float2 csub(float2 a, float2 b) { return make_float2(a.x - b.x, a.y - b.y); }
__device__ __forceinline__ float2 cmul(float2 a, float2 b) {
    return make_float2(fmaf(a.x, b.x, -a.y * b.y), fmaf(a.x, b.y, a.y * b.x));
}
__device__ __forceinline__ float2 conjf2(float2 a) { return make_float2(a.x, -a.y); }
__device__ __forceinline__ float4 pack2(float2 a, float2 b) { return make_float4(a.x, a.y, b.x, b.y); }

template <int DIR>
__device__ __forceinline__ float2 mulJ(float2 a) {
    return (DIR < 0) ? make_float2(a.y, -a.x) : make_float2(-a.y, a.x);
}

template <int DIR>
__device__ __forceinline__ void dft4(float2* v) {
    float2 s0 = cadd(v[0], v[2]), d0 = csub(v[0], v[2]);
    float2 s1 = cadd(v[1], v[3]), d1 = mulJ<DIR>(csub(v[1], v[3]));
    v[0] = cadd(s0, s1);
    v[1] = cadd(d0, d1);
    v[2] = csub(s0, s1);
    v[3] = csub(d0, d1);
}

template <int DIR>
__device__ __forceinline__ void dft8(float2* v) {
    const float HC = 0.70710678118654752f;
    float2 b0 = cadd(v[0], v[4]);
    float2 b1 = cadd(v[1], v[5]);
    float2 b2 = cadd(v[2], v[6]);
    float2 b3 = cadd(v[3], v[7]);
    float2 c0 = csub(v[0], v[4]);
    float2 c1 = cmul(csub(v[1], v[5]), make_float2(HC, DIR * HC));
    float2 c2 = mulJ<DIR>(csub(v[2], v[6]));
    float2 c3 = cmul(csub(v[3], v[7]), make_float2(-HC, DIR * HC));
    {
        float2 s0 = cadd(b0, b2), d0 = csub(b0, b2);
        float2 s1 = cadd(b1, b3), d1 = mulJ<DIR>(csub(b1, b3));
        v[0] = cadd(s0, s1);
        v[2] = cadd(d0, d1);
        v[4] = csub(s0, s1);
        v[6] = csub(d0, d1);
    }
    {
        float2 s0 = cadd(c0, c2), d0 = csub(c0, c2);
        float2 s1 = cadd(c1, c3), d1 = mulJ<DIR>(csub(c1, c3));
        v[1] = cadd(s0, s1);
        v[3] = cadd(d0, d1);
        v[5] = csub(s0, s1);
        v[7] = csub(d0, d1);
    }
}

// 16-point DFT in registers: two radix-4 levels (Stockham, self-sorting).
template <int DIR>
__device__ __forceinline__ void dft16(float2* v) {
    const float C1 = 0.92387953251128675f;
    const float S1 = 0.38268343236508977f;
    const float H2 = 0.70710678118654752f;
    const float2 W1 = make_float2(C1, DIR * S1);
    const float2 W2 = make_float2(H2, DIR * H2);
    const float2 W3 = make_float2(S1, DIR * C1);
    const float2 W6 = make_float2(-H2, DIR * H2);
    const float2 W9 = make_float2(-C1, -DIR * S1);

    float2 u[16];
#pragma unroll
    for (int i = 0; i < 4; i++) {
        float2 a[4] = {v[i], v[i + 4], v[i + 8], v[i + 12]};
        dft4<DIR>(a);
        u[4 * i + 0] = a[0];
        u[4 * i + 1] = a[1];
        u[4 * i + 2] = a[2];
        u[4 * i + 3] = a[3];
    }
    {
        float2 a[4] = {u[0], u[4], u[8], u[12]};
        dft4<DIR>(a);
        v[0] = a[0]; v[4] = a[1]; v[8] = a[2]; v[12] = a[3];
    }
    {
        float2 a[4] = {u[1], cmul(u[5], W1), cmul(u[9], W2), cmul(u[13], W3)};
        dft4<DIR>(a);
        v[1] = a[0]; v[5] = a[1]; v[9] = a[2]; v[13] = a[3];
    }
    {
        float2 a[4] = {u[2], cmul(u[6], W2), mulJ<DIR>(u[10]), cmul(u[14], W6)};
        dft4<DIR>(a);
        v[2] = a[0]; v[6] = a[1]; v[10] = a[2]; v[14] = a[3];
    }
    {
        float2 a[4] = {u[3], cmul(u[7], W3), cmul(u[11], W6), cmul(u[15], W9)};
        dft4<DIR>(a);
        v[3] = a[0]; v[7] = a[1]; v[11] = a[2]; v[15] = a[3];
    }
}

// Fwd stage 1: radix-16, NS=1, reads global. Output 18*tl+r contiguous -> STS.128.
__device__ __forceinline__ void stage_f1(const float2* __restrict__ in,
                                         float2* __restrict__ out, int tl) {
    float2 v[16];
#pragma unroll
    for (int r = 0; r < 16; r++) v[r] = in[tl + (r << 7)];
    dft16<-1>(v);
    float4* __restrict__ o4 = reinterpret_cast<float4*>(out) + 9 * tl;
#pragma unroll
    for (int q = 0; q < 8; q++) o4[q] = pack2(v[2 * q], v[2 * q + 1]);
}

// Inv stage 1: radix-16, NS=1, reads CONTIGUOUS layout (slot 18*tl+r holds
// D[tl+128r]) via LDS.128; writes 18*tl+r contiguous via STS.128.
__device__ __forceinline__ void stage_i1(const float2* __restrict__ in,
                                         float2* __restrict__ out, int tl) {
    float2 v[16];
    const float4* __restrict__ i4 = reinterpret_cast<const float4*>(in) + 9 * tl;
#pragma unroll
    for (int q = 0; q < 8; q++) {
        float4 f = i4[q];
        v[2 * q] = make_float2(f.x, f.y);
        v[2 * q + 1] = make_float2(f.z, f.w);
    }
    dft16<1>(v);
    float4* __restrict__ o4 = reinterpret_cast<float4*>(out) + 9 * tl;
#pragma unroll
    for (int q = 0; q < 8; q++) o4[q] = pack2(v[2 * q], v[2 * q + 1]);
}

// Stage 2: radix-16, NS=16. Dual-chain twiddle powers.
template <int DIR>
__device__ __forceinline__ void stage_r16_ns16(const float2* __restrict__ in,
                                               float2* __restrict__ out, int tl, float2 wb) {
    float2 v[16];
#pragma unroll
    for (int r = 0; r < 16; r++) v[r] = in[pd(tl + (r << 7))];
    {
        float2 p2 = cmul(wb, wb);
        float2 wo = wb;
        float2 we = p2;
        v[1] = cmul(v[1], wo);
        v[2] = cmul(v[2], we);
#pragma unroll
        for (int r = 3; r < 16; r += 2) {
            wo = cmul(wo, p2);
            v[r] = cmul(v[r], wo);
            if (r + 1 < 16) {
                we = cmul(we, p2);
                v[r + 1] = cmul(v[r + 1], we);
            }
        }
    }
    dft16<DIR>(v);
    const int jm = tl & 15, jd = tl >> 4;
    const int o = (jd << 8) + jm;
#pragma unroll
    for (int r = 0; r < 16; r++) out[pd(o + (r << 4))] = v[r];
}

// Stage 3: radix-8, NS=256. Two butterflies per thread. Dual-chain twiddles.
// GOUT: write to global with bias add (coalesced).
template <int DIR, bool GOUT>
__device__ __forceinline__ void stage_r8_ns256(const float2* __restrict__ in,
                                               float2* __restrict__ out, int tl,
                                               float2 wA, float2 wB, float bv) {
#pragma unroll
    for (int h = 0; h < 2; h++) {
        const int j = tl + (h << 7);
        const float2 wb = h ? wB : wA;
        float2 v[8];
#pragma unroll
        for (int r = 0; r < 8; r++) v[r] = in[pd(j + (r << 8))];
        {
            float2 p2 = cmul(wb, wb);
            float2 wo = wb;
            float2 we = p2;
            v[1] = cmul(v[1], wo);
            v[2] = cmul(v[2], we);
            wo = cmul(wo, p2); v[3] = cmul(v[3], wo);
            we = cmul(we, p2); v[4] = cmul(v[4], we);
            wo = cmul(wo, p2); v[5] = cmul(v[5], wo);
            we = cmul(we, p2); v[6] = cmul(v[6], we);
            wo = cmul(wo, p2); v[7] = cmul(v[7], wo);
        }
        dft8<DIR>(v);
#pragma unroll
        for (int r = 0; r < 8; r++) {
            if (GOUT)
                out[j + (r << 8)] = make_float2(v[r].x + bv, v[r].y + bv);
            else
                out[pd(j + (r << 8))] = v[r];
        }
    }
}

// Untangle rfft, multiply by H, repack one-sided for inverse.
// Writes the CONTIGUOUS inv-s1 layout: bin t+128r -> slot 18t+r.
__device__ __forceinline__ void midstage(const float2* __restrict__ S, float2* __restrict__ Dc,
                                         const float2* __restrict__ Hs, int tl, float2 wqb) {
    const float MCC[8] = {1.0f, 0.98078528040323044f, 0.92387953251128675f, 0.83146961230254524f,
                          0.70710678118654752f, 0.55557023301960222f, 0.38268343236508977f, 0.19509032201612827f};
    const float MCS[8] = {0.0f, -0.19509032201612827f, -0.38268343236508977f, -0.55557023301960222f,
                          -0.70710678118654752f, -0.83146961230254524f, -0.92387953251128675f, -0.98078528040323044f};
    float2 mainv[8], mirv[8];
#pragma unroll
    for (int i = 0; i < 8; i++) {
        const int k = tl + (i << 7);
        const float2 wq = cmul(wqb, make_float2(MCC[i], MCS[i]));  // e^{-2pi*i*k/4096}
        float2 Zk = S[pd(k)];
        float2 Zm = S[pd((2048 - k) & 2047)];
        float2 E = make_float2(0.5f * (Zk.x + Zm.x), 0.5f * (Zk.y - Zm.y));
        float2 O = make_float2(0.5f * (Zk.y + Zm.y), -0.5f * (Zk.x - Zm.x));
        float2 Xk = cadd(E, cmul(O, wq));
        float2 Yk = cmul(Xk, Hs[k]);
        const float sc = 1.0f / 4096.0f;
        Yk.x *= sc;
        Yk.y *= sc;
        const float cph = wq.x, sph = -wq.y;
        mainv[i] = cmul(Yk, make_float2(1.0f - sph, cph));
        mirv[i] = cmul(conjf2(Yk), make_float2(1.0f + sph, cph));
    }
    float4* __restrict__ m4 = reinterpret_cast<float4*>(Dc) + 9 * tl;
#pragma unroll
    for (int q = 0; q < 4; q++) m4[q] = pack2(mainv[2 * q], mainv[2 * q + 1]);
    if (tl > 0) {
        float4* __restrict__ r4 = reinterpret_cast<float4*>(Dc) + 9 * (128 - tl) + 4;
#pragma unroll
        for (int q = 0; q < 4; q++) r4[q] = pack2(mirv[7 - 2 * q], mirv[6 - 2 * q]);
    } else {
        float2 w[8];
        w[0] = make_float2(0.0f, 0.0f);
#pragma unroll
        for (int i = 1; i < 8; i++) w[8 - i] = mirv[i];
        float4* __restrict__ r4 = reinterpret_cast<float4*>(Dc) + 4;
#pragma unroll
        for (int q = 0; q < 4; q++) r4[q] = pack2(w[2 * q], w[2 * q + 1]);
    }
}

__global__ void reset_row_counter_kernel() { g_row_counter = 0; }

__global__ void __launch_bounds__(NTHREADS, 4)
spectral_circulant_kernel(const float* __restrict__ x, const float* __restrict__ wre,
                          const float* __restrict__ wim, const float* __restrict__ bias,
                          float* __restrict__ out, int nrows) {
    extern __shared__ float2 sm[];
    __shared__ int sh_row;
    float2* X = sm;
    float2* Y = sm + SB16;
    float2* Hs = sm + 2 * SB16;  // 1024 float2
    const int tl = threadIdx.x;  // 0..127

    for (int k = tl; k < 1024; k += NTHREADS) Hs[k] = make_float2(__ldg(wre + k), __ldg(wim + k));
    const float bv = __ldg(bias);

    // Per-thread twiddle bases (row-invariant)
    float s, c;
    sincospif(-(float)(tl & 15) * (1.0f / 128.0f), &s, &c);
    const float2 w2f = make_float2(c, s);  // e^{-2pi*i*(tl&15)/256}
    sincospif(-(float)tl * (1.0f / 1024.0f), &s, &c);
    const float2 w3f = make_float2(c, s);  // e^{-2pi*i*tl/2048}
    sincospif(-(float)tl * (1.0f / 2048.0f), &s, &c);
    const float2 wqb = make_float2(c, s);  // e^{-2pi*i*tl/4096}
    const float2 E8 = make_float2(0.92387953251128675f, -0.38268343236508977f);  // e^{-i*pi/8}
    const float2 w3g = cmul(w3f, E8);
    const float2 w2i = conjf2(w2f);
    const float2 w3i = conjf2(w3f);
    const float2 w3gi = conjf2(w3g);

    // Fetch first row.
    if (tl == 0) sh_row = atomicAdd(&g_row_counter, 1);
    __syncthreads();  // Hs + sh_row visible

    for (;;) {
        const int row = sh_row;  // all threads read before any barrier below
        if (row >= nrows) break;
        const float2* xin = reinterpret_cast<const float2*>(x) + (size_t)row * 2048;
        float2* yout = reinterpret_cast<float2*>(out) + (size_t)row * 2048;

        // Forward c2c-2048: G -> Y -> X -> Y
        stage_f1(xin, Y, tl);
        __syncthreads();
        // Prefetch next row index; consumed at the next loop-top (5 barriers
        // away), so atomic latency is hidden and ordering is safe: every
        // thread already captured `row` before this barrier.
        if (tl == 0) sh_row = atomicAdd(&g_row_counter, 1);
        stage_r16_ns16<-1>(Y, X, tl, w2f);
        __syncthreads();
        stage_r8_ns256<-1, false>(X, Y, tl, w3f, w3g, 0.0f);
        __syncthreads();

        // Mid: Y -> X (contiguous inv-s1 layout)
        midstage(Y, X, Hs, tl, wqb);
        __syncthreads();

        // Inverse c2c-2048: X -> Y -> X -> G
        stage_i1(X, Y, tl);
        __syncthreads();
        stage_r16_ns16<1>(Y, X, tl, w2i);
        __syncthreads();
        stage_r8_ns256<1, true>(X, yout, tl, w3i, w3gi, bv);
        // no trailing barrier: this stage's X reads precede the barrier after
        // the next row's stage 1 (which writes Y); X is next written only
        // after a later barrier. sh_row was last written before this
        // iteration's stage-2 barrier, so the loop-top read is ordered.
    }
}

extern "C" void kernel_launch(void* const* d_in, const int* in_sizes, int n_in,
                              void* d_out, int out_size) {
    const float* x = (const float*)d_in[0];
    const float* wre = (const float*)d_in[1];
    const float* wim = (const float*)d_in[2];
    const float* bias = (const float*)d_in[3];
    float* out = (float*)d_out;

    const int nrows = in_sizes[0] / 4096;  // 8192
    const int smem_bytes = (2 * SB16 + 1024) * sizeof(float2);  // 45056

    static int grid = 0;
    if (grid == 0) {
        cudaFuncSetAttribute(spectral_circulant_kernel,
                             cudaFuncAttributeMaxDynamicSharedMemorySize, smem_bytes);
        int nsm = 148;
        cudaDeviceGetAttribute(&nsm, cudaDevAttrMultiProcessorCount, 0);
        grid = 4 * nsm;  // persistent, 4 CTAs/SM (1 row each)
    }

    reset_row_counter_kernel<<<1, 1>>>();
    spectral_circulant_kernel<<<grid, NTHREADS, smem_bytes>>>(x, wre, wim, bias, out, nrows);
}